// round 7
// baseline (speedup 1.0000x reference)
#include <cuda_runtime.h>

#define N_GOAL 16384
#define N_OBS  65536
#define N_TASK 8192
#define NE1    1048576
#define NE2    1048576
#define FDIM   128
#define SDIM   64
#define CAP1   64
#define CAP2   256

typedef unsigned long long ull;

// Scratch (static device globals — no runtime allocation)
__device__ float g_pg  [N_GOAL * SDIM];   // x_goal @ W1        (4 MB)
__device__ float g_buf1[N_OBS * SDIM];    // x_obs  @ W1        (16 MB)
__device__ float g_x1  [N_OBS * SDIM];    // x1 activations     (16 MB)
__device__ int   g_cnt1[N_OBS];
__device__ int   g_cnt2[N_TASK];
__device__ int   g_bkt1[N_OBS * CAP1];    // (16 MB)
__device__ int   g_bkt2[N_TASK * CAP2];   // (8 MB)

__device__ __forceinline__ float4 f4add(float4 a, float4 b) {
    a.x += b.x; a.y += b.y; a.z += b.z; a.w += b.w; return a;
}
__device__ __forceinline__ float4 f4biasrelu(float4 a, float4 b) {
    a.x = fmaxf(a.x + b.x, 0.f); a.y = fmaxf(a.y + b.y, 0.f);
    a.z = fmaxf(a.z + b.z, 0.f); a.w = fmaxf(a.w + b.w, 0.f);
    return a;
}
// Packed f32x2 FMA (Blackwell): d = a*b + c lane-wise on two packed floats.
__device__ __forceinline__ ull ffma2(ull a, ull b, ull c) {
    ull d;
    asm("fma.rn.f32x2 %0, %1, %2, %3;" : "=l"(d) : "l"(a), "l"(b), "l"(c));
    return d;
}
__device__ __forceinline__ float2 unpack2(ull v) {
    float2 f;
    asm("mov.b64 {%0, %1}, %2;" : "=f"(f.x), "=f"(f.y) : "l"(v));
    return f;
}

// ---------------------------------------------------------------------------
__global__ void zero_counts() {
    int i = blockIdx.x * blockDim.x + threadIdx.x;
    if (i < N_OBS) g_cnt1[i] = 0;
    if (i < N_TASK) g_cnt2[i] = 0;
}

// One pass over both edge sets; one 4B atomic per edge.
__global__ void build_all(const int* __restrict__ s1, const int* __restrict__ d1,
                          const int* __restrict__ s2, const int* __restrict__ d2) {
    int e = blockIdx.x * blockDim.x + threadIdx.x;
    if (e < NE1) {
        int s = s1[e], d = d1[e];
        int slot = atomicAdd(&g_cnt1[d], 1);
        if (slot < CAP1) g_bkt1[d * CAP1 + slot] = s;
    } else {
        int e2 = e - NE1;
        int s = s2[e2], d = d2[e2];
        int slot = atomicAdd(&g_cnt2[d], 1);
        if (slot < CAP2) g_bkt2[d * CAP2 + slot] = s;
    }
}

// ---------------------------------------------------------------------------
// projAll: rows 0..N_GOAL-1 from x_goal -> pg, rest from x_obs -> buf1.
// f32x2 packed-along-K. X read directly from gmem (warp-broadcast, L1-reused);
// only W is staged (K-transposed) in smem.
#define XP 132
__global__ __launch_bounds__(256, 5) void projAll(const float* __restrict__ xg,
                                                  const float* __restrict__ xo,
                                                  const float* __restrict__ W,
                                                  float* __restrict__ pg,
                                                  float* __restrict__ buf1) {
    __shared__ float Wt[SDIM * XP];   // Wt[c][k]  (33792 B)
    int t = threadIdx.x;
    for (int i = t; i < FDIM * SDIM; i += 256) {
        int k = i >> 6, c = i & 63;
        Wt[c * XP + k] = W[i];
    }
    __syncthreads();

    const float* X; float* out; int rowbase;
    if (blockIdx.x < N_GOAL / 64) { X = xg; out = pg; rowbase = blockIdx.x * 64; }
    else { X = xo; out = buf1; rowbase = (blockIdx.x - N_GOAL / 64) * 64; }

    int warp = t >> 5, lane = t & 31;
    int row0 = rowbase + warp * 8;

    ull acc0[8], acc1[8];
#pragma unroll
    for (int i = 0; i < 8; i++) { acc0[i] = 0ull; acc1[i] = 0ull; }

    const float* xb = X + (size_t)row0 * FDIM;
#pragma unroll 4
    for (int k = 0; k < FDIM; k += 4) {
        ulonglong2 wA = *(const ulonglong2*)&Wt[lane * XP + k];
        ulonglong2 wB = *(const ulonglong2*)&Wt[(lane + 32) * XP + k];
#pragma unroll
        for (int i = 0; i < 8; i++) {
            ulonglong2 xh = *(const ulonglong2*)&xb[i * FDIM + k];  // broadcast
            acc0[i] = ffma2(xh.x, wA.x, acc0[i]);
            acc0[i] = ffma2(xh.y, wA.y, acc0[i]);
            acc1[i] = ffma2(xh.x, wB.x, acc1[i]);
            acc1[i] = ffma2(xh.y, wB.y, acc1[i]);
        }
    }
#pragma unroll
    for (int i = 0; i < 8; i++) {
        float2 fa = unpack2(acc0[i]);
        float2 fb = unpack2(acc1[i]);
        out[(size_t)(row0 + i) * SDIM + lane]      = fa.x + fa.y;
        out[(size_t)(row0 + i) * SDIM + lane + 32] = fb.x + fb.y;
    }
}

// ---------------------------------------------------------------------------
// g1mlp1: per block of 32 obs rows:
//   gather (8 thr/row, int2 idx prefetch): h = buf1[d] + sum pg[s]
//   layer1: h = relu(h + b1) -> smem
//   layer2: x1 = relu(h @ W2 + b2)  (f32x2 packed-along-K, warp = 4 rows)
#define HST 68
__global__ __launch_bounds__(256, 6) void g1mlp1(const float* __restrict__ b1,
                                                 const float* __restrict__ W2,
                                                 const float* __restrict__ b2) {
    __shared__ float Hs[32 * HST];        // 8704 B
    __shared__ float W2t[SDIM * HST];     // 17408 B, W2t[c][k]
    int t = threadIdx.x;
    for (int i = t; i < SDIM * SDIM; i += 256) {
        int k = i >> 6, c = i & 63;
        W2t[c * HST + k] = W2[i];
    }

    // ---- gather: r = local row (32), q = f4 chunk (8) ----
    int r = t >> 3, q = t & 7;
    int d = blockIdx.x * 32 + r;
    int n = g_cnt1[d]; if (n > CAP1) n = CAP1;
    const float4* pgf = (const float4*)g_pg;
    const float4* bf  = (const float4*)g_buf1;
    float4 a0 = bf[d * 16 + q];
    float4 a1 = bf[d * 16 + q + 8];
    const int* bkt = g_bkt1 + d * CAP1;
    int j = 0;
    for (; j + 2 <= n; j += 2) {
        int2 s2 = *(const int2*)(bkt + j);
        float4 v00 = pgf[s2.x * 16 + q], v01 = pgf[s2.x * 16 + q + 8];
        float4 v10 = pgf[s2.y * 16 + q], v11 = pgf[s2.y * 16 + q + 8];
        a0 = f4add(a0, f4add(v00, v10));
        a1 = f4add(a1, f4add(v01, v11));
    }
    if (j < n) {
        int s = bkt[j];
        a0 = f4add(a0, pgf[s * 16 + q]);
        a1 = f4add(a1, pgf[s * 16 + q + 8]);
    }
    const float4* b1f = (const float4*)b1;
    a0 = f4biasrelu(a0, b1f[q]);
    a1 = f4biasrelu(a1, b1f[q + 8]);
    *(float4*)&Hs[r * HST + 4 * q]       = a0;
    *(float4*)&Hs[r * HST + 4 * (q + 8)] = a1;
    __syncthreads();

    // ---- GEMM: warp owns 4 rows; lane owns cols {lane, lane+32} ----
    int warp = t >> 5, lane = t & 31;
    ull acc0[4] = {0ull, 0ull, 0ull, 0ull};
    ull acc1[4] = {0ull, 0ull, 0ull, 0ull};
    const float* hb = Hs + warp * 4 * HST;
#pragma unroll
    for (int k = 0; k < SDIM; k += 4) {
        ulonglong2 wA = *(const ulonglong2*)&W2t[lane * HST + k];
        ulonglong2 wB = *(const ulonglong2*)&W2t[(lane + 32) * HST + k];
#pragma unroll
        for (int i = 0; i < 4; i++) {
            ulonglong2 xh = *(const ulonglong2*)&hb[i * HST + k];
            acc0[i] = ffma2(xh.x, wA.x, acc0[i]);
            acc0[i] = ffma2(xh.y, wA.y, acc0[i]);
            acc1[i] = ffma2(xh.x, wB.x, acc1[i]);
            acc1[i] = ffma2(xh.y, wB.y, acc1[i]);
        }
    }
    int row0 = blockIdx.x * 32 + warp * 4;
    float b2a = b2[lane], b2b = b2[lane + 32];
#pragma unroll
    for (int i = 0; i < 4; i++) {
        float2 fa = unpack2(acc0[i]);
        float2 fb = unpack2(acc1[i]);
        g_x1[(size_t)(row0 + i) * SDIM + lane]      = fmaxf(fa.x + fa.y + b2a, 0.f);
        g_x1[(size_t)(row0 + i) * SDIM + lane + 32] = fmaxf(fb.x + fb.y + b2b, 0.f);
    }
}

// ---------------------------------------------------------------------------
// g2mlp2: block = one graph = 32 contiguous task rows, 512 threads.
//   gather (16 thr/row, int4 idx prefetch): x = x_task[d] + sum x1[s]
//   mlp:    thread = (row, 4 cols), f32x2 along K; W4 dot; 16-lane reduce
//   pool:   max/mean over 32 rows, critic head -> out[graph]
#define XSTR 68
#define W3S  68
__global__ __launch_bounds__(512) void g2mlp2(const float4* __restrict__ x_task,
                                              const float* __restrict__ W3,
                                              const float* __restrict__ b3,
                                              const float* __restrict__ W4,
                                              const float* __restrict__ b4,
                                              const float* __restrict__ Wc1,
                                              const float* __restrict__ bc1,
                                              const float* __restrict__ Wc2,
                                              const float* __restrict__ bc2,
                                              float* __restrict__ out) {
    __shared__ float Xs[32 * XSTR];       // 8704 B
    __shared__ float W3t[SDIM * W3S];     // 17408 B, W3t[c][k]
    __shared__ float W4s[SDIM], b3s[SDIM];
    __shared__ float scal[32];
    int t = threadIdx.x;
    for (int i = t; i < SDIM * SDIM; i += 512) {
        int k = i >> 6, c = i & 63;
        W3t[c * W3S + k] = W3[i];
    }
    if (t < SDIM) { W4s[t] = W4[t]; b3s[t] = b3[t]; }

    // ---- gather: r = local row (32), q = f4 chunk (16) ----
    int r = t >> 4, q = t & 15;
    int d = blockIdx.x * 32 + r;
    int n = g_cnt2[d]; if (n > CAP2) n = CAP2;
    const float4* x1f = (const float4*)g_x1;
    float4 a0 = x_task[d * 16 + q];
    const int* bkt = g_bkt2 + d * CAP2;
    int j = 0;
    for (; j + 4 <= n; j += 4) {
        int4 s4 = *(const int4*)(bkt + j);
        float4 v0 = x1f[s4.x * 16 + q];
        float4 v1 = x1f[s4.y * 16 + q];
        float4 v2 = x1f[s4.z * 16 + q];
        float4 v3 = x1f[s4.w * 16 + q];
        a0 = f4add(f4add(a0, v0), f4add(v1, f4add(v2, v3)));
    }
    for (; j < n; j++) a0 = f4add(a0, x1f[bkt[j] * 16 + q]);
    *(float4*)&Xs[r * XSTR + 4 * q] = a0;
    __syncthreads();

    // ---- mlp: thread = (row r, cols cbase..cbase+3), f32x2 along K ----
    int cbase = q * 4;
    ull acc[4] = {0ull, 0ull, 0ull, 0ull};
    const float* xrow = Xs + r * XSTR;
#pragma unroll
    for (int k = 0; k < SDIM; k += 4) {
        ulonglong2 xh = *(const ulonglong2*)&xrow[k];
#pragma unroll
        for (int i = 0; i < 4; i++) {
            ulonglong2 w = *(const ulonglong2*)&W3t[(cbase + i) * W3S + k];
            acc[i] = ffma2(xh.x, w.x, acc[i]);
            acc[i] = ffma2(xh.y, w.y, acc[i]);
        }
    }
    float partial = 0.f;
#pragma unroll
    for (int i = 0; i < 4; i++) {
        float2 f = unpack2(acc[i]);
        float s = f.x + f.y + b3s[cbase + i];
        partial = fmaf(fmaxf(s, 0.f), W4s[cbase + i], partial);
    }
#pragma unroll
    for (int o = 1; o < 16; o <<= 1)
        partial += __shfl_xor_sync(0xffffffffu, partial, o);
    if (q == 0) scal[r] = partial + b4[0];
    __syncthreads();

    // ---- pooling + critic (warp 0) ----
    if (t < 32) {
        float v = scal[t];
        float vmax = v, vsum = v;
#pragma unroll
        for (int o = 16; o; o >>= 1) {
            vmax = fmaxf(vmax, __shfl_xor_sync(0xffffffffu, vmax, o));
            vsum += __shfl_xor_sync(0xffffffffu, vsum, o);
        }
        if (t == 0) {
            float mx = vmax;
            float mn = vsum * (1.f / 32.f);
            float rr = bc2[0];
#pragma unroll
            for (int i = 0; i < 8; i++) {
                float h = fmaxf(fmaf(mx, Wc1[i], fmaf(mn, Wc1[8 + i], bc1[i])), 0.f);
                rr = fmaf(h, Wc2[i], rr);
            }
            out[blockIdx.x] = rr;
        }
    }
}

// ---------------------------------------------------------------------------
extern "C" void kernel_launch(void* const* d_in, const int* in_sizes, int n_in,
                              void* d_out, int out_size) {
    const float* x_goal = (const float*)d_in[0];
    const float* x_obs  = (const float*)d_in[1];
    const float* x_task = (const float*)d_in[2];
    const int* ei_go_src = (const int*)d_in[3];
    const int* ei_go_dst = (const int*)d_in[4];
    const int* ei_ot_src = (const int*)d_in[5];
    const int* ei_ot_dst = (const int*)d_in[6];
    // d_in[7] = task_batch (contiguous; unused)
    const float* W1  = (const float*)d_in[8];
    const float* b1  = (const float*)d_in[9];
    const float* W2  = (const float*)d_in[10];
    const float* b2  = (const float*)d_in[11];
    const float* W3  = (const float*)d_in[12];
    const float* b3  = (const float*)d_in[13];
    const float* W4  = (const float*)d_in[14];
    const float* b4  = (const float*)d_in[15];
    const float* Wc1 = (const float*)d_in[16];
    const float* bc1 = (const float*)d_in[17];
    const float* Wc2 = (const float*)d_in[18];
    const float* bc2 = (const float*)d_in[19];
    float* out = (float*)d_out;

    float* pg   = nullptr; cudaGetSymbolAddress((void**)&pg,   g_pg);
    float* buf1 = nullptr; cudaGetSymbolAddress((void**)&buf1, g_buf1);

    // 1. zero counters
    zero_counts<<<N_OBS / 256, 256>>>();
    // 2. bucket both edge sets
    build_all<<<(NE1 + NE2) / 256, 256>>>(ei_go_src, ei_go_dst, ei_ot_src, ei_ot_dst);
    // 3. pg = x_goal @ W1 ; buf1 = x_obs @ W1   (f32x2 GEMM, gmem-broadcast X)
    projAll<<<(N_GOAL + N_OBS) / 64, 256>>>(x_goal, x_obs, W1, pg, buf1);
    // 4. gather1 + MLP1 fused -> x1
    g1mlp1<<<N_OBS / 32, 256>>>(b1, W2, b2);
    // 5. gather2 + MLP2 + pooling + critic fused -> out
    g2mlp2<<<N_TASK / 32, 512>>>((const float4*)x_task, W3, b3, W4, b4,
                                 Wc1, bc1, Wc2, bc2, out);
}

// round 8
// speedup vs baseline: 1.4405x; 1.4405x over previous
#include <cuda_runtime.h>

#define N_GOAL 16384
#define N_OBS  65536
#define N_TASK 8192
#define NE1    1048576
#define NE2    1048576
#define FDIM   128
#define SDIM   64
#define CAP1   64
#define CAP2   256

typedef unsigned long long ull;

// Scratch (static device globals — no runtime allocation)
__device__ float g_pg  [N_GOAL * SDIM];   // x_goal @ W1        (4 MB)
__device__ float g_buf1[N_OBS * SDIM];    // x_obs  @ W1        (16 MB)
__device__ float g_x1  [N_OBS * SDIM];    // x1 activations     (16 MB)
__device__ int   g_cnt1[N_OBS];
__device__ int   g_cnt2[N_TASK];
__device__ int   g_bkt1[N_OBS * CAP1];    // (16 MB)
__device__ int   g_bkt2[N_TASK * CAP2];   // (8 MB)

__device__ __forceinline__ float4 f4add(float4 a, float4 b) {
    a.x += b.x; a.y += b.y; a.z += b.z; a.w += b.w; return a;
}
__device__ __forceinline__ float4 f4biasrelu(float4 a, float4 b) {
    a.x = fmaxf(a.x + b.x, 0.f); a.y = fmaxf(a.y + b.y, 0.f);
    a.z = fmaxf(a.z + b.z, 0.f); a.w = fmaxf(a.w + b.w, 0.f);
    return a;
}
// Packed f32x2 FMA (Blackwell): d = a*b + c lane-wise on two packed floats.
__device__ __forceinline__ ull ffma2(ull a, ull b, ull c) {
    ull d;
    asm("fma.rn.f32x2 %0, %1, %2, %3;" : "=l"(d) : "l"(a), "l"(b), "l"(c));
    return d;
}
__device__ __forceinline__ float2 unpack2(ull v) {
    float2 f;
    asm("mov.b64 {%0, %1}, %2;" : "=f"(f.x), "=f"(f.y) : "l"(v));
    return f;
}

// ---------------------------------------------------------------------------
__global__ void zero_counts() {
    int i = blockIdx.x * blockDim.x + threadIdx.x;
    if (i < N_OBS) g_cnt1[i] = 0;
    if (i < N_TASK) g_cnt2[i] = 0;
}

// One pass over both edge sets; one 4B atomic per edge.
__global__ void build_all(const int* __restrict__ s1, const int* __restrict__ d1,
                          const int* __restrict__ s2, const int* __restrict__ d2) {
    int e = blockIdx.x * blockDim.x + threadIdx.x;
    if (e < NE1) {
        int s = s1[e], d = d1[e];
        int slot = atomicAdd(&g_cnt1[d], 1);
        if (slot < CAP1) g_bkt1[d * CAP1 + slot] = s;
    } else {
        int e2 = e - NE1;
        int s = s2[e2], d = d2[e2];
        int slot = atomicAdd(&g_cnt2[d], 1);
        if (slot < CAP2) g_bkt2[d * CAP2 + slot] = s;
    }
}

// ---------------------------------------------------------------------------
// projAll (Round-5 proven version): rows 0..N_GOAL-1 -> pg, rest -> buf1.
// f32x2 packed-along-K. X staged row-major in smem; W staged K-transposed.
#define XP 132
__global__ __launch_bounds__(256) void projAll(const float* __restrict__ xg,
                                               const float* __restrict__ xo,
                                               const float* __restrict__ W,
                                               float* __restrict__ pg,
                                               float* __restrict__ buf1) {
    extern __shared__ float sm[];
    float* Xs = sm;                 // 64 rows x XP   (33792 B)
    float* Wt = sm + 64 * XP;       // Wt[c][k], 64 x XP (33792 B)
    int t = threadIdx.x;

    for (int i = t; i < FDIM * SDIM; i += 256) {
        int k = i >> 6, c = i & 63;
        Wt[c * XP + k] = W[i];
    }

    const float* X; float* out; int rowbase;
    if (blockIdx.x < N_GOAL / 64) { X = xg; out = pg; rowbase = blockIdx.x * 64; }
    else { X = xo; out = buf1; rowbase = (blockIdx.x - N_GOAL / 64) * 64; }

    const float4* X4 = (const float4*)(X + (size_t)rowbase * FDIM);
    for (int i = t; i < 64 * 32; i += 256) {
        int row = i >> 5, kq = i & 31;
        *(float4*)&Xs[row * XP + kq * 4] = X4[row * 32 + kq];
    }
    __syncthreads();

    int warp = t >> 5, lane = t & 31;
    ull acc0[8], acc1[8];
#pragma unroll
    for (int i = 0; i < 8; i++) { acc0[i] = 0ull; acc1[i] = 0ull; }

    const float* xb = Xs + warp * 8 * XP;
#pragma unroll 4
    for (int k = 0; k < FDIM; k += 4) {
        ulonglong2 wA = *(const ulonglong2*)&Wt[lane * XP + k];
        ulonglong2 wB = *(const ulonglong2*)&Wt[(lane + 32) * XP + k];
#pragma unroll
        for (int i = 0; i < 8; i++) {
            ulonglong2 xh = *(const ulonglong2*)&xb[i * XP + k];
            acc0[i] = ffma2(xh.x, wA.x, acc0[i]);
            acc0[i] = ffma2(xh.y, wA.y, acc0[i]);
            acc1[i] = ffma2(xh.x, wB.x, acc1[i]);
            acc1[i] = ffma2(xh.y, wB.y, acc1[i]);
        }
    }
    int row0 = rowbase + warp * 8;
#pragma unroll
    for (int i = 0; i < 8; i++) {
        float2 fa = unpack2(acc0[i]);
        float2 fb = unpack2(acc1[i]);
        out[(size_t)(row0 + i) * SDIM + lane]      = fa.x + fa.y;
        out[(size_t)(row0 + i) * SDIM + lane + 32] = fb.x + fb.y;
    }
}

// ---------------------------------------------------------------------------
// g1mlp1: 512 threads, 32 obs rows/block.
//   gather: 16 thr/row (one f4 chunk each), int4 idx prefetch ->
//           4 independent LDG.128 in flight/thread, 64/row.
//   layer1: h = relu(h + b1) -> smem
//   layer2: x1 = relu(h @ W2 + b2)  (f32x2 along K, warp = 2 rows)
#define HST 68
__global__ __launch_bounds__(512) void g1mlp1(const float* __restrict__ b1,
                                              const float* __restrict__ W2,
                                              const float* __restrict__ b2) {
    __shared__ float Hs[32 * HST];        // 8704 B
    __shared__ float W2t[SDIM * HST];     // 17408 B, W2t[c][k]
    int t = threadIdx.x;
    for (int i = t; i < SDIM * SDIM; i += 512) {
        int k = i >> 6, c = i & 63;
        W2t[c * HST + k] = W2[i];
    }

    // ---- gather: r = local row (32), q = f4 chunk (16) ----
    int r = t >> 4, q = t & 15;
    int d = blockIdx.x * 32 + r;
    int n = g_cnt1[d]; if (n > CAP1) n = CAP1;
    const float4* pgf = (const float4*)g_pg;
    float4 acc = ((const float4*)g_buf1)[d * 16 + q];
    const int* bkt = g_bkt1 + d * CAP1;
    int j = 0;
    for (; j + 4 <= n; j += 4) {
        int4 s4 = *(const int4*)(bkt + j);
        float4 v0 = pgf[s4.x * 16 + q];
        float4 v1 = pgf[s4.y * 16 + q];
        float4 v2 = pgf[s4.z * 16 + q];
        float4 v3 = pgf[s4.w * 16 + q];
        acc = f4add(f4add(acc, v0), f4add(v1, f4add(v2, v3)));
    }
    for (; j < n; j++) acc = f4add(acc, pgf[bkt[j] * 16 + q]);
    acc = f4biasrelu(acc, ((const float4*)b1)[q]);
    *(float4*)&Hs[r * HST + 4 * q] = acc;
    __syncthreads();

    // ---- GEMM: 16 warps, warp owns 2 rows; lane owns cols {lane, lane+32} ----
    int warp = t >> 5, lane = t & 31;
    ull acc0[2] = {0ull, 0ull};
    ull acc1[2] = {0ull, 0ull};
    const float* hb = Hs + warp * 2 * HST;
#pragma unroll
    for (int k = 0; k < SDIM; k += 4) {
        ulonglong2 wA = *(const ulonglong2*)&W2t[lane * HST + k];
        ulonglong2 wB = *(const ulonglong2*)&W2t[(lane + 32) * HST + k];
#pragma unroll
        for (int i = 0; i < 2; i++) {
            ulonglong2 xh = *(const ulonglong2*)&hb[i * HST + k];
            acc0[i] = ffma2(xh.x, wA.x, acc0[i]);
            acc0[i] = ffma2(xh.y, wA.y, acc0[i]);
            acc1[i] = ffma2(xh.x, wB.x, acc1[i]);
            acc1[i] = ffma2(xh.y, wB.y, acc1[i]);
        }
    }
    int row0 = blockIdx.x * 32 + warp * 2;
    float b2a = b2[lane], b2b = b2[lane + 32];
#pragma unroll
    for (int i = 0; i < 2; i++) {
        float2 fa = unpack2(acc0[i]);
        float2 fb = unpack2(acc1[i]);
        g_x1[(size_t)(row0 + i) * SDIM + lane]      = fmaxf(fa.x + fa.y + b2a, 0.f);
        g_x1[(size_t)(row0 + i) * SDIM + lane + 32] = fmaxf(fb.x + fb.y + b2b, 0.f);
    }
}

// ---------------------------------------------------------------------------
// g2mlp2 (Round-5 proven version): block = one graph = 32 task rows, 256 thr.
#define XSTR 68
#define WSTR 65
__global__ __launch_bounds__(256) void g2mlp2(const float4* __restrict__ x_task,
                                              const float* __restrict__ W3,
                                              const float* __restrict__ b3,
                                              const float* __restrict__ W4,
                                              const float* __restrict__ b4,
                                              const float* __restrict__ Wc1,
                                              const float* __restrict__ bc1,
                                              const float* __restrict__ Wc2,
                                              const float* __restrict__ bc2,
                                              float* __restrict__ out) {
    __shared__ float Xs[32 * XSTR];
    __shared__ float W3t[SDIM * WSTR];    // transposed [c][k]
    __shared__ float W4s[SDIM], b3s[SDIM];
    __shared__ float scal[32];
    int t = threadIdx.x;
    for (int i = t; i < SDIM * SDIM; i += 256) {
        int k = i >> 6, c = i & 63;
        W3t[c * WSTR + k] = W3[i];
    }
    if (t < SDIM) { W4s[t] = W4[t]; b3s[t] = b3[t]; }

    // ---- gather: r = local row, q = chunk (8) ----
    int r = t >> 3, q = t & 7;
    int d = blockIdx.x * 32 + r;
    int n = g_cnt2[d]; if (n > CAP2) n = CAP2;
    const float4* x1f = (const float4*)g_x1;
    float4 a0 = x_task[d * 16 + q];
    float4 a1 = x_task[d * 16 + q + 8];
    const int* bkt = g_bkt2 + d * CAP2;
    int j = 0;
    for (; j + 4 <= n; j += 4) {
        int4 s4 = *(const int4*)(bkt + j);
        float4 v00 = x1f[s4.x * 16 + q], v01 = x1f[s4.x * 16 + q + 8];
        float4 v10 = x1f[s4.y * 16 + q], v11 = x1f[s4.y * 16 + q + 8];
        float4 v20 = x1f[s4.z * 16 + q], v21 = x1f[s4.z * 16 + q + 8];
        float4 v30 = x1f[s4.w * 16 + q], v31 = x1f[s4.w * 16 + q + 8];
        a0 = f4add(f4add(a0, v00), f4add(v10, f4add(v20, v30)));
        a1 = f4add(f4add(a1, v01), f4add(v11, f4add(v21, v31)));
    }
    for (; j < n; j++) {
        int s = bkt[j];
        a0 = f4add(a0, x1f[s * 16 + q]);
        a1 = f4add(a1, x1f[s * 16 + q + 8]);
    }
    float* xp = Xs + r * XSTR + 4 * q;
    *(float4*)(xp)      = a0;
    *(float4*)(xp + 32) = a1;
    __syncthreads();

    // ---- mlp: row = t>>3, 8 output cols per thread ----
    float s8[8];
    int cbase = q * 8;
#pragma unroll
    for (int i = 0; i < 8; i++) s8[i] = b3s[cbase + i];
    const float* xrow = Xs + r * XSTR;
#pragma unroll 4
    for (int k = 0; k < SDIM; k++) {
        float xv = xrow[k];
#pragma unroll
        for (int i = 0; i < 8; i++)
            s8[i] = fmaf(xv, W3t[(cbase + i) * WSTR + k], s8[i]);
    }
    float partial = 0.f;
#pragma unroll
    for (int i = 0; i < 8; i++)
        partial = fmaf(fmaxf(s8[i], 0.f), W4s[cbase + i], partial);
#pragma unroll
    for (int o = 1; o < 8; o <<= 1)
        partial += __shfl_xor_sync(0xffffffffu, partial, o);
    if (q == 0) scal[r] = partial + b4[0];
    __syncthreads();

    // ---- pooling + critic (warp 0) ----
    if (t < 32) {
        float v = scal[t];
        float vmax = v, vsum = v;
#pragma unroll
        for (int o = 16; o; o >>= 1) {
            vmax = fmaxf(vmax, __shfl_xor_sync(0xffffffffu, vmax, o));
            vsum += __shfl_xor_sync(0xffffffffu, vsum, o);
        }
        if (t == 0) {
            float mx = vmax;
            float mn = vsum * (1.f / 32.f);
            float rr = bc2[0];
#pragma unroll
            for (int i = 0; i < 8; i++) {
                float h = fmaxf(fmaf(mx, Wc1[i], fmaf(mn, Wc1[8 + i], bc1[i])), 0.f);
                rr = fmaf(h, Wc2[i], rr);
            }
            out[blockIdx.x] = rr;
        }
    }
}

// ---------------------------------------------------------------------------
extern "C" void kernel_launch(void* const* d_in, const int* in_sizes, int n_in,
                              void* d_out, int out_size) {
    const float* x_goal = (const float*)d_in[0];
    const float* x_obs  = (const float*)d_in[1];
    const float* x_task = (const float*)d_in[2];
    const int* ei_go_src = (const int*)d_in[3];
    const int* ei_go_dst = (const int*)d_in[4];
    const int* ei_ot_src = (const int*)d_in[5];
    const int* ei_ot_dst = (const int*)d_in[6];
    // d_in[7] = task_batch (contiguous; unused)
    const float* W1  = (const float*)d_in[8];
    const float* b1  = (const float*)d_in[9];
    const float* W2  = (const float*)d_in[10];
    const float* b2  = (const float*)d_in[11];
    const float* W3  = (const float*)d_in[12];
    const float* b3  = (const float*)d_in[13];
    const float* W4  = (const float*)d_in[14];
    const float* b4  = (const float*)d_in[15];
    const float* Wc1 = (const float*)d_in[16];
    const float* bc1 = (const float*)d_in[17];
    const float* Wc2 = (const float*)d_in[18];
    const float* bc2 = (const float*)d_in[19];
    float* out = (float*)d_out;

    float* pg   = nullptr; cudaGetSymbolAddress((void**)&pg,   g_pg);
    float* buf1 = nullptr; cudaGetSymbolAddress((void**)&buf1, g_buf1);

    const int PROJ_SMEM = 2 * 64 * XP * sizeof(float);   // 67584 B
    cudaFuncSetAttribute(projAll, cudaFuncAttributeMaxDynamicSharedMemorySize,
                         PROJ_SMEM);

    // 1. zero counters
    zero_counts<<<N_OBS / 256, 256>>>();
    // 2. bucket both edge sets
    build_all<<<(NE1 + NE2) / 256, 256>>>(ei_go_src, ei_go_dst, ei_ot_src, ei_ot_dst);
    // 3. pg = x_goal @ W1 ; buf1 = x_obs @ W1   (f32x2 GEMM, staged smem)
    projAll<<<(N_GOAL + N_OBS) / 64, 256, PROJ_SMEM>>>(x_goal, x_obs, W1, pg, buf1);
    // 4. gather1 + MLP1 fused -> x1
    g1mlp1<<<N_OBS / 32, 512>>>(b1, W2, b2);
    // 5. gather2 + MLP2 + pooling + critic fused -> out
    g2mlp2<<<N_TASK / 32, 256>>>((const float4*)x_task, W3, b3, W4, b4,
                                 Wc1, bc1, Wc2, bc2, out);
}